// round 17
// baseline (speedup 1.0000x reference)
#include <cuda_runtime.h>
#include <cuda_fp16.h>
#include <cstdint>
#include <math.h>

// ---------------- problem dims (Qwen3-Omni Talker SparseMoeBlock) ------------
#define T_  2048   // tokens
#define H_  2048   // hidden
#define I_  1408   // routed intermediate
#define IS_ 5632   // shared intermediate
#define E_  32     // experts
#define TK_ 4      // top-k

// ---------------- static scratch (no allocations allowed) --------------------
__device__ __align__(16) __half g_hh[11534336];   // silu output, fp16
__device__ __align__(16) float  g_y[16777216];    // 8192 * 2048 pair outputs

// fp16 pre-converted operands (gate/up pair-interleaved for GEMM1 weights)
__device__ __align__(16) __half g_xh[4194304];      // x          [T,H]
__device__ __align__(16) __half g_wguh[184549376];  // w_gate_up  [E,H,2I] pairs
__device__ __align__(16) __half g_wdh[92274688];    // w_down     [E,I,H]
__device__ __align__(16) __half g_sguh[23068672];   // shared_gu  [H,2IS] pairs
__device__ __align__(16) __half g_sdh[11534336];    // shared_dn  [IS,H]

__device__ int   g_topk_idx[T_ * TK_];
__device__ float g_topk_w[T_ * TK_];
__device__ float g_sgate[T_];
__device__ int   g_cnt[E_];
__device__ int   g_off[E_ + 1];
__device__ int   g_pair_token[T_ * TK_];
__device__ float g_pair_w[T_ * TK_];
__device__ int   g_slot[T_ * TK_];

// ---------------- f32 -> f16 bulk convert -------------------------------------
__global__ void f2h_kernel(const float* __restrict__ src, __half* __restrict__ dst,
                           long long n8) {
    const long long i = (long long)blockIdx.x * blockDim.x + threadIdx.x;
    if (i >= n8) return;
    const float4 a = *(const float4*)(src + i * 8);
    const float4 b = *(const float4*)(src + i * 8 + 4);
    __half2 h0 = __floats2half2_rn(a.x, a.y);
    __half2 h1 = __floats2half2_rn(a.z, a.w);
    __half2 h2 = __floats2half2_rn(b.x, b.y);
    __half2 h3 = __floats2half2_rn(b.z, b.w);
    uint4 o;
    o.x = *reinterpret_cast<uint32_t*>(&h0);
    o.y = *reinterpret_cast<uint32_t*>(&h1);
    o.z = *reinterpret_cast<uint32_t*>(&h2);
    o.w = *reinterpret_cast<uint32_t*>(&h3);
    *(uint4*)(dst + i * 8) = o;
}

// f32 [rows, 2*inter] (gate | up halves) -> f16 [rows, 2*inter] pair-interleaved:
// dst[r][2j] = gate[r][j], dst[r][2j+1] = up[r][j]
__global__ void f2h_pair_kernel(const float* __restrict__ src,
                                __half* __restrict__ dst,
                                int inter, long long n4) {
    const long long i = (long long)blockIdx.x * blockDim.x + threadIdx.x;
    if (i >= n4) return;
    const long long row = i / (inter / 4);
    const int j4 = (int)(i % (inter / 4)) * 4;
    const float* base = src + row * (2LL * inter);
    const float4 g = *(const float4*)(base + j4);
    const float4 u = *(const float4*)(base + inter + j4);
    __half2 p0 = __floats2half2_rn(g.x, u.x);
    __half2 p1 = __floats2half2_rn(g.y, u.y);
    __half2 p2 = __floats2half2_rn(g.z, u.z);
    __half2 p3 = __floats2half2_rn(g.w, u.w);
    uint4 o;
    o.x = *reinterpret_cast<uint32_t*>(&p0);
    o.y = *reinterpret_cast<uint32_t*>(&p1);
    o.z = *reinterpret_cast<uint32_t*>(&p2);
    o.w = *reinterpret_cast<uint32_t*>(&p3);
    *(uint4*)(dst + row * (2LL * inter) + 2 * j4) = o;
}

// ---------------- router: logits -> softmax top4 -> renorm + sigmoid gate ----
__global__ void router_kernel(const float* __restrict__ x,
                              const float* __restrict__ gate_w,
                              const float* __restrict__ sgate_w) {
    const int t = blockIdx.x;
    const float* xr = x + (size_t)t * H_;
    __shared__ float xs[H_];
    __shared__ float logits[E_];
    __shared__ float red[256];
    const int tid = threadIdx.x;

    for (int i = tid * 4; i < H_; i += 256 * 4) {
        *(float4*)(xs + i) = *(const float4*)(xr + i);
    }
    __syncthreads();

    const int wid = tid >> 5, lane = tid & 31;
    const int ebase = wid * 4;
    float a0 = 0.f, a1 = 0.f, a2 = 0.f, a3 = 0.f;
    for (int h = lane; h < H_; h += 32) {
        const float xv = xs[h];
        const float* gw = gate_w + (size_t)h * E_ + ebase;
        a0 += xv * gw[0]; a1 += xv * gw[1];
        a2 += xv * gw[2]; a3 += xv * gw[3];
    }
    #pragma unroll
    for (int o = 16; o; o >>= 1) {
        a0 += __shfl_xor_sync(~0u, a0, o);
        a1 += __shfl_xor_sync(~0u, a1, o);
        a2 += __shfl_xor_sync(~0u, a2, o);
        a3 += __shfl_xor_sync(~0u, a3, o);
    }
    if (lane == 0) {
        logits[ebase + 0] = a0; logits[ebase + 1] = a1;
        logits[ebase + 2] = a2; logits[ebase + 3] = a3;
    }

    float p = 0.f;
    for (int h = tid; h < H_; h += 256) p += xs[h] * sgate_w[h];
    red[tid] = p;
    __syncthreads();
    #pragma unroll
    for (int s = 128; s; s >>= 1) {
        if (tid < s) red[tid] += red[tid + s];
        __syncthreads();
    }

    if (tid == 0) {
        g_sgate[t] = 1.f / (1.f + expf(-red[0]));
        float l[E_];
        #pragma unroll
        for (int e = 0; e < E_; e++) l[e] = logits[e];
        int   idx[TK_];
        float val[TK_];
        #pragma unroll
        for (int k = 0; k < TK_; k++) {
            int bi = 0; float bv = -1e30f;
            for (int e = 0; e < E_; e++)
                if (l[e] > bv) { bv = l[e]; bi = e; }
            idx[k] = bi; val[k] = bv; l[bi] = -1e30f;
        }
        const float mx = val[0];
        float s = 0.f, w[TK_];
        #pragma unroll
        for (int k = 0; k < TK_; k++) { w[k] = expf(val[k] - mx); s += w[k]; }
        const float inv = 1.f / s;
        #pragma unroll
        for (int k = 0; k < TK_; k++) {
            g_topk_idx[t * TK_ + k] = idx[k];
            g_topk_w[t * TK_ + k]   = w[k] * inv;
        }
    }
}

// ---------------- per-expert counts + exclusive scan (1 block) ---------------
__global__ void count_scan_kernel() {
    __shared__ int sc[E_];
    const int tid = threadIdx.x;
    if (tid < E_) sc[tid] = 0;
    __syncthreads();
    for (int i = tid; i < T_ * TK_; i += 256)
        atomicAdd(&sc[g_topk_idx[i]], 1);
    __syncthreads();
    if (tid == 0) {
        int run = 0;
        for (int e = 0; e < E_; e++) {
            g_off[e] = run;
            g_cnt[e] = sc[e];
            run += sc[e];
        }
        g_off[E_] = run;
    }
}

// ---------------- deterministic bucketing: 1 warp per expert -----------------
__global__ void bucket_kernel() {
    const int e = blockIdx.x;
    const int lane = threadIdx.x;
    const int base = g_off[e];
    int cnt = 0;
    for (int t0 = 0; t0 < T_; t0 += 32) {
        const int t = t0 + lane;
        int km = -1; float w = 0.f;
        #pragma unroll
        for (int k = 0; k < TK_; k++)
            if (g_topk_idx[t * TK_ + k] == e) { km = k; w = g_topk_w[t * TK_ + k]; }
        const unsigned mask = __ballot_sync(~0u, km >= 0);
        if (km >= 0) {
            const int p = base + cnt + __popc(mask & ((1u << lane) - 1));
            g_pair_token[p] = t;
            g_pair_w[p]     = w;
            g_slot[t * TK_ + km] = p;
        }
        cnt += __popc(mask);
    }
}

// ================= fp16 HMMA GEMM: 4-stage cp.async + ldmatrix ===============
#define BM 128
#define BN 256
#define BK 32
#define NSTG 4
#define SAH 40    // A smem row stride in halfs (80B: conflict-free ldmatrix)
#define SBH 264   // B smem row stride in halfs (528B: conflict-free ldmatrix)
#define ABUFB (BM * SAH * 2)            // 10240 B
#define BBUFB (BK * SBH * 2)            // 16896 B
#define STAGEB (ABUFB + BBUFB)          // 27136 B
#define SMEM_BYTES (NSTG * STAGEB)      // 108544 B

__device__ __forceinline__ void ldm_x4(uint32_t* r, uint32_t addr) {
    asm volatile("ldmatrix.sync.aligned.m8n8.x4.shared.b16 {%0,%1,%2,%3}, [%4];"
                 : "=r"(r[0]), "=r"(r[1]), "=r"(r[2]), "=r"(r[3]) : "r"(addr));
}
__device__ __forceinline__ void ldm_x4_t(uint32_t* r, uint32_t addr) {
    asm volatile("ldmatrix.sync.aligned.m8n8.x4.trans.shared.b16 {%0,%1,%2,%3}, [%4];"
                 : "=r"(r[0]), "=r"(r[1]), "=r"(r[2]), "=r"(r[3]) : "r"(addr));
}
__device__ __forceinline__ void mma_f16(float* c, const uint32_t* a, const uint32_t* b) {
    asm volatile(
        "mma.sync.aligned.m16n8k16.row.col.f32.f16.f16.f32 "
        "{%0,%1,%2,%3}, {%4,%5,%6,%7}, {%8,%9}, {%0,%1,%2,%3};"
        : "+f"(c[0]), "+f"(c[1]), "+f"(c[2]), "+f"(c[3])
        : "r"(a[0]), "r"(a[1]), "r"(a[2]), "r"(a[3]), "r"(b[0]), "r"(b[1]));
}
__device__ __forceinline__ void cp16(uint32_t dst, const void* src) {
    asm volatile("cp.async.cg.shared.global [%0], [%1], 16;" :: "r"(dst), "l"(src));
}

// MODE 0: shared GEMM1  g_hh[T,IS]  = silu_mul(xh @ sgu_pairs)       (fused)
// MODE 1: shared GEMM2  out[T,H]    = (g_hh @ shared_down) * sgate[t]
// MODE 2: routed GEMM1  g_hh[p,I]   = silu_mul(gather(xh) @ wgu_pairs[e])
// MODE 3: routed GEMM2  y[p,H]      = (g_hh @ w_down[e]) * pair_w[p]
template<int MODE>
__global__ void __launch_bounds__(256)
gemm_cp(const __half* __restrict__ Bh, float* __restrict__ Carg)
{
    constexpr int N  = (MODE == 0) ? 2 * IS_ : (MODE == 2) ? 2 * I_ : H_;
    constexpr int Kd = (MODE == 0) ? H_ : (MODE == 1) ? IS_ : (MODE == 2) ? H_ : I_;
    constexpr int nK = Kd / BK;
    constexpr bool FUSE = (MODE == 0 || MODE == 2);   // silu-pair epilogue

    const __half* Ab = (MODE == 1 || MODE == 3) ? (const __half*)g_hh
                                                 : (const __half*)g_xh;
    float* Cb = (MODE == 1) ? Carg : (float*)g_y;

    const int tid  = threadIdx.x;
    const int wid  = tid >> 5;
    const int lane = tid & 31;
    const int m0 = blockIdx.x * BM;   // m fastest: consecutive CTAs share B in L2
    const int n0 = blockIdx.y * BN;
    int Mcnt = T_, rowoff = 0;
    const __half* B = Bh;
    if (MODE >= 2) {
        const int e = blockIdx.z;
        Mcnt = g_cnt[e];
        if (m0 >= Mcnt) return;       // early-exit empty tiles
        rowoff = g_off[e];
        B = Bh + (size_t)e * ((size_t)Kd * N);
    }

    extern __shared__ __half smh[];
    const uint32_t sbase = (uint32_t)__cvta_generic_to_shared(smh);

    // ---- staging assignments ----
    const int arow = tid & 127;
    const int ack  = tid >> 7;
    const __half* aSrc;
    {
        int lr = m0 + arow;
        if (lr >= Mcnt) lr = Mcnt - 1;     // safe duplicate; masked in epilogue
        int grow;
        if (MODE == 2)      grow = g_pair_token[rowoff + lr];
        else if (MODE == 3) grow = rowoff + lr;
        else                grow = lr;
        aSrc = Ab + (size_t)grow * Kd + ack * 16;
    }
    const uint32_t aDst = sbase + arow * (SAH * 2) + ack * 32;
    const int bk  = tid >> 3;
    const int bg  = tid & 7;
    const __half* bSrc = B + (size_t)bk * N + n0 + bg * 8;
    const uint32_t bDst = sbase + ABUFB + bk * (SBH * 2) + bg * 16;

    auto stage = [&](int kt) {
        const uint32_t so = (kt % NSTG) * STAGEB;
        const __half* as = aSrc + kt * BK;
        cp16(aDst + so,      as);
        cp16(aDst + so + 16, as + 8);
        const __half* bs = bSrc + (size_t)kt * BK * N;
        #pragma unroll
        for (int i = 0; i < 4; i++)
            cp16(bDst + so + i * 128, bs + i * 64);
        asm volatile("cp.async.commit_group;");
    };

    // ---- per-warp mma geometry: 2(M) x 4(N) warps, 64x64 tiles ----
    const int wm = (wid & 1) * 64;
    const int wn = (wid >> 1) * 64;
    const int q  = lane >> 3;
    const int r7 = lane & 7;
    const int lrow = (q & 1) * 8 + r7;
    const int lcol = (q >> 1) * 8;

    float acc[4][8][4];
    #pragma unroll
    for (int i = 0; i < 4; i++)
        #pragma unroll
        for (int j = 0; j < 8; j++)
            #pragma unroll
            for (int c = 0; c < 4; c++) acc[i][j][c] = 0.f;

    auto compute = [&](int kt) {
        const uint32_t aB = sbase + (kt % NSTG) * STAGEB;
        const uint32_t bB = aB + ABUFB;
        #pragma unroll
        for (int ks = 0; ks < 2; ks++) {
            uint32_t af[4][4], bf[4][4];
            #pragma unroll
            for (int mt = 0; mt < 4; mt++)
                ldm_x4(af[mt], aB + ((wm + mt * 16 + lrow) * SAH + ks * 16 + lcol) * 2);
            #pragma unroll
            for (int p = 0; p < 4; p++)
                ldm_x4_t(bf[p], bB + ((ks * 16 + lrow) * SBH + wn + p * 16 + lcol) * 2);
            #pragma unroll
            for (int mt = 0; mt < 4; mt++)
                #pragma unroll
                for (int nt = 0; nt < 8; nt++)
                    mma_f16(acc[mt][nt], af[mt], &bf[nt >> 1][(nt & 1) * 2]);
        }
    };

    // ---- 4-stage pipeline, ONE sync per K-tile ----
    stage(0); stage(1); stage(2);
    for (int kt = 0; kt < nK; kt++) {
        const int rem = nK - 1 - kt;      // groups staged beyond kt
        if (rem >= 3)      asm volatile("cp.async.wait_group 2;");
        else if (rem == 2) asm volatile("cp.async.wait_group 2;");
        else if (rem == 1) asm volatile("cp.async.wait_group 1;");
        else               asm volatile("cp.async.wait_group 0;");
        __syncthreads();                  // also guards buffer (kt+3)%4 reuse
        if (kt + 3 < nK) stage(kt + 3);
        compute(kt);
    }

    // ---- epilogue ----
    const int fr = lane >> 2;
    const int fc = lane & 3;
    #pragma unroll
    for (int mt = 0; mt < 4; mt++) {
        #pragma unroll
        for (int half = 0; half < 2; half++) {
            const int rloc = wm + mt * 16 + fr + half * 8;
            const int lr = m0 + rloc;
            if (lr >= Mcnt) continue;
            if (FUSE) {
                // pair-interleaved: (c0,c1) = (gate, up) for pair j = cc/2
                const size_t crow = (MODE == 2) ? (size_t)(rowoff + lr) : (size_t)lr;
                __half* Hrow = g_hh + crow * (N / 2) + n0 / 2;
                #pragma unroll
                for (int nt = 0; nt < 8; nt++) {
                    const int cc = wn + nt * 8 + fc * 2;
                    const float g = acc[mt][nt][half * 2 + 0];
                    const float u = acc[mt][nt][half * 2 + 1];
                    Hrow[cc / 2] = __float2half_rn(g / (1.f + expf(-g)) * u);
                }
            } else {
                float s;
                size_t crow;
                if (MODE == 1) { s = g_sgate[lr]; crow = (size_t)lr; }
                else           { crow = (size_t)(rowoff + lr); s = g_pair_w[rowoff + lr]; }
                float* Crow = Cb + crow * N + n0;
                #pragma unroll
                for (int nt = 0; nt < 8; nt++) {
                    const int cc = wn + nt * 8 + fc * 2;
                    float2 v;
                    v.x = acc[mt][nt][half * 2 + 0] * s;
                    v.y = acc[mt][nt][half * 2 + 1] * s;
                    *(float2*)(Crow + cc) = v;
                }
            }
        }
    }
}

// ---------------- final combine: out += sum_k y[slot[t][k]] --------------------
__global__ void reduce_kernel(float* __restrict__ out) {
    const int i = blockIdx.x * blockDim.x + threadIdx.x;  // over T*H/4
    const int t = i / (H_ / 4);
    const int c = (i % (H_ / 4)) * 4;
    const int* sl = g_slot + t * TK_;
    float* op = out + (size_t)t * H_ + c;
    float4 a = *(float4*)op;
    #pragma unroll
    for (int k = 0; k < TK_; k++) {
        const float4 y = *(const float4*)(g_y + (size_t)sl[k] * H_ + c);
        a.x += y.x; a.y += y.y; a.z += y.z; a.w += y.w;
    }
    *(float4*)op = a;
}

// ---------------- launch ------------------------------------------------------
extern "C" void kernel_launch(void* const* d_in, const int* in_sizes, int n_in,
                              void* d_out, int out_size) {
    const float* x   = (const float*)d_in[0];
    const float* gw  = (const float*)d_in[1];
    const float* wgu = (const float*)d_in[2];
    const float* wd  = (const float*)d_in[3];
    const float* sgu = (const float*)d_in[4];
    const float* sd  = (const float*)d_in[5];
    const float* sg  = (const float*)d_in[6];
    float* out = (float*)d_out;
    (void)in_sizes; (void)n_in; (void)out_size;

    cudaFuncSetAttribute(gemm_cp<0>, cudaFuncAttributeMaxDynamicSharedMemorySize, SMEM_BYTES);
    cudaFuncSetAttribute(gemm_cp<1>, cudaFuncAttributeMaxDynamicSharedMemorySize, SMEM_BYTES);
    cudaFuncSetAttribute(gemm_cp<2>, cudaFuncAttributeMaxDynamicSharedMemorySize, SMEM_BYTES);
    cudaFuncSetAttribute(gemm_cp<3>, cudaFuncAttributeMaxDynamicSharedMemorySize, SMEM_BYTES);

    // resolve device-symbol addresses (host API, graph-capture safe)
    __half *xh, *wguh, *wdh, *sguh, *sdh;
    cudaGetSymbolAddress((void**)&xh,   g_xh);
    cudaGetSymbolAddress((void**)&wguh, g_wguh);
    cudaGetSymbolAddress((void**)&wdh,  g_wdh);
    cudaGetSymbolAddress((void**)&sguh, g_sguh);
    cudaGetSymbolAddress((void**)&sdh,  g_sdh);

    // fp16 conversion passes (GEMM1 weights pair-interleaved)
    f2h_kernel<<<(4194304 / 8 + 255) / 256, 256>>>(x, xh, 4194304 / 8);
    f2h_pair_kernel<<<(int)((184549376LL / 8 + 255) / 256), 256>>>(
        wgu, wguh, I_, 184549376LL / 8);
    f2h_kernel<<<(int)((92274688LL / 8 + 255) / 256), 256>>>(wd, wdh, 92274688LL / 8);
    f2h_pair_kernel<<<(23068672 / 8 + 255) / 256, 256>>>(sgu, sguh, IS_, 23068672 / 8);
    f2h_kernel<<<(11534336 / 8 + 255) / 256, 256>>>(sd, sdh, 11534336 / 8);

    // router + deterministic bucketing
    router_kernel<<<T_, 256>>>(x, gw, sg);
    count_scan_kernel<<<1, 256>>>();
    bucket_kernel<<<E_, 32>>>();

    // routed experts (grouped, gathered rows, fused silu in GEMM1)
    gemm_cp<2><<<dim3(T_ / BM, 2 * I_ / BN, E_), 256, SMEM_BYTES>>>(wguh, nullptr);
    gemm_cp<3><<<dim3(T_ / BM, H_ / BN, E_), 256, SMEM_BYTES>>>(wdh, nullptr);

    // shared expert (dense, fused silu in GEMM1) -> out = shared (sigmoid-gated)
    gemm_cp<0><<<dim3(T_ / BM, 2 * IS_ / BN, 1), 256, SMEM_BYTES>>>(sguh, nullptr);
    gemm_cp<1><<<dim3(T_ / BM, H_ / BN, 1), 256, SMEM_BYTES>>>(sdh, out);

    // out += routed combine
    reduce_kernel<<<T_ * H_ / 4 / 256, 256>>>(out);
}